// round 14
// baseline (speedup 1.0000x reference)
#include <cuda_runtime.h>
#include <math.h>

#define F_IN   512
#define HID    16
#define CLS    40
#define N_MAX  100000
#define E_MAX  3400000
#define SCAN_B 1024
#define NBLK   ((N_MAX + SCAN_B - 1) / SCAN_B)   // 98

// ---------------- scratch (static device globals; no allocation) ------------
__device__ float  g_dis[N_MAX];                 // dis = rsqrt(deg)
__device__ int    g_cnt[N_MAX];                 // in-degree counts
__device__ int    g_off[N_MAX + 1];             // CSR offsets (by col)
__device__ int    g_cursor[N_MAX];              // fill cursors
__device__ int    g_bsum[NBLK];                 // per-block totals
__device__ int    g_boff[NBLK];                 // per-block exclusive offsets
__device__ unsigned long long g_csr[E_MAX];     // packed (w_bits<<32 | row)
__device__ float4 g_h1[N_MAX * 4];              // h1 partials, then dis*h1
__device__ float4 g_h2[N_MAX * 4];              // hd2 = dis*relu(layer1)

// ---------------- helpers ---------------------------------------------------
__device__ __forceinline__ unsigned long long pack2(float lo, float hi) {
    unsigned long long d;
    asm("mov.b64 %0, {%1,%2};" : "=l"(d) : "f"(lo), "f"(hi));
    return d;
}
__device__ __forceinline__ void unpack2(unsigned long long v, float& lo, float& hi) {
    asm("mov.b64 {%0,%1}, %2;" : "=f"(lo), "=f"(hi) : "l"(v));
}
__device__ __forceinline__ unsigned long long fma2(unsigned long long a,
                                                   unsigned long long b,
                                                   unsigned long long c) {
    unsigned long long d;
    asm("fma.rn.f32x2 %0, %1, %2, %3;" : "=l"(d) : "l"(a), "l"(b), "l"(c));
    return d;
}
__device__ __forceinline__ void red_add_v4(float4* addr, float x, float y, float z, float w) {
    asm volatile("red.global.add.v4.f32 [%0], {%1,%2,%3,%4};"
                 :: "l"(addr), "f"(x), "f"(y), "f"(z), "f"(w)
                 : "memory");
}

// ---------------- init: cnt=0, h1=0 (red.add target) ------------------------
__global__ void init_kernel(int N) {
    int i = blockIdx.x * blockDim.x + threadIdx.x;
    if (i < N * 4) g_h1[i] = make_float4(0.f, 0.f, 0.f, 0.f);
    if (i < N) g_cnt[i] = 0;
}

// cnt[col] += 1
__global__ void cnt_kernel(const int* __restrict__ col, int E) {
    int e = blockIdx.x * blockDim.x + threadIdx.x;
    if (e < E) atomicAdd(&g_cnt[col[e]], 1);
}

// ---------------- 3-phase multi-block exclusive scan ------------------------
__global__ __launch_bounds__(SCAN_B) void scan1_kernel(int N) {
    __shared__ int s[SCAN_B];
    int t = threadIdx.x;
    int i = blockIdx.x * SCAN_B + t;
    int v = (i < N) ? g_cnt[i] : 0;
    s[t] = v;
    __syncthreads();
    #pragma unroll
    for (int d = 1; d < SCAN_B; d <<= 1) {
        int u = (t >= d) ? s[t - d] : 0;
        __syncthreads();
        s[t] += u;
        __syncthreads();
    }
    if (i < N) g_off[i] = s[t] - v;                 // exclusive
    if (t == SCAN_B - 1) g_bsum[blockIdx.x] = s[t]; // block total
}

__global__ __launch_bounds__(128) void scan2_kernel(int N) {
    __shared__ int s[128];
    int t = threadIdx.x;
    int v = (t < NBLK) ? g_bsum[t] : 0;
    s[t] = v;
    __syncthreads();
    #pragma unroll
    for (int d = 1; d < 128; d <<= 1) {
        int u = (t >= d) ? s[t - d] : 0;
        __syncthreads();
        s[t] += u;
        __syncthreads();
    }
    if (t < NBLK) g_boff[t] = s[t] - v;
    if (t == 127) g_off[N] = s[t];                  // grand total (= E)
}

__global__ void scan3_kernel(int N) {
    int i = blockIdx.x * blockDim.x + threadIdx.x;
    if (i < N) {
        int o = g_off[i] + g_boff[i / SCAN_B];
        g_off[i] = o;
        g_cursor[i] = o;
    }
}

// fill CSR: append (w, row) to col c
__global__ void fill_kernel(const int* __restrict__ ei, const float* __restrict__ w, int E) {
    int e = blockIdx.x * blockDim.x + threadIdx.x;
    if (e >= E) return;
    int r = ei[e];
    int c = ei[E + e];
    int pos = atomicAdd(&g_cursor[c], 1);
    g_csr[pos] = ((unsigned long long)__float_as_uint(w[e]) << 32) | (unsigned int)r;
}

// ---------------- dense GEMM: h1 += x @ W1  (K-split, f32x2, red.add) -------
#define GT     256                 // threads per block (8 warps)
#define ROWS_B 512                 // rows per block = 256 packed pairs
#define KC     16                  // k-chunk
#define XPAD   4                   // row stride KC+4 = 20 floats = 80B (16B-aligned)
#define KSPLIT 4
#define KPB    (F_IN / KSPLIT)     // 128 K per block

__global__ __launch_bounds__(GT) void gemm1_kernel(const float* __restrict__ x,
                                                   const float* __restrict__ W1,
                                                   int N) {
    __shared__ float xs[ROWS_B][KC + XPAD];        // 40 KB
    __shared__ unsigned long long ws2[KC][HID];    // W duplicated (w,w), 2 KB
    int r0 = blockIdx.x * ROWS_B;
    int k0 = blockIdx.y * KPB;

    unsigned long long acc2[HID];
    #pragma unroll
    for (int j = 0; j < HID; j++) acc2[j] = 0ULL;

    for (int kc = k0; kc < k0 + KPB; kc += KC) {
        __syncthreads();
        {   // 256 threads load 256 W elements
            int i = threadIdx.x;
            float wv = W1[(kc + i / HID) * HID + (i % HID)];
            ws2[i / HID][i % HID] = pack2(wv, wv);
        }
        #pragma unroll
        for (int l = 0; l < (ROWS_B * (KC / 4)) / GT; l++) {   // 8 float4 each
            int idx = l * GT + threadIdx.x;
            int rl  = idx / (KC / 4);
            int c4  = idx % (KC / 4);
            int row = r0 + rl;
            float4 v = make_float4(0.f, 0.f, 0.f, 0.f);
            if (row < N)
                v = *(const float4*)(x + (size_t)row * F_IN + kc + c4 * 4);
            *(float4*)&xs[rl][c4 * 4] = v;                      // STS.128
        }
        __syncthreads();

        #pragma unroll
        for (int k4 = 0; k4 < KC / 4; k4++) {
            float4 xa4 = *(const float4*)&xs[threadIdx.x][k4 * 4];        // LDS.128
            float4 xb4 = *(const float4*)&xs[threadIdx.x + 256][k4 * 4];  // LDS.128
            float xa[4] = {xa4.x, xa4.y, xa4.z, xa4.w};
            float xb[4] = {xb4.x, xb4.y, xb4.z, xb4.w};
            #pragma unroll
            for (int ki = 0; ki < 4; ki++) {
                int kk = k4 * 4 + ki;
                unsigned long long xp = pack2(xa[ki], xb[ki]);
                #pragma unroll
                for (int m = 0; m < HID / 2; m++) {
                    ulonglong2 w2 = *(const ulonglong2*)&ws2[kk][2 * m];  // LDS.128
                    acc2[2 * m + 0] = fma2(xp, w2.x, acc2[2 * m + 0]);
                    acc2[2 * m + 1] = fma2(xp, w2.y, acc2[2 * m + 1]);
                }
            }
        }
    }

    float va[HID], vb[HID];
    #pragma unroll
    for (int j = 0; j < HID; j++) unpack2(acc2[j], va[j], vb[j]);
    int rowA = r0 + threadIdx.x;
    int rowB = r0 + threadIdx.x + 256;
    if (rowA < N) {
        #pragma unroll
        for (int q = 0; q < 4; q++)
            red_add_v4(&g_h1[rowA * 4 + q], va[4*q], va[4*q+1], va[4*q+2], va[4*q+3]);
    }
    if (rowB < N) {
        #pragma unroll
        for (int q = 0; q < 4; q++)
            red_add_v4(&g_h1[rowB * 4 + q], vb[4*q], vb[4*q+1], vb[4*q+2], vb[4*q+3]);
    }
}

// ---------------- deg from CSR; dis = rsqrt; scale h1 *= dis (warp/node) ----
__global__ __launch_bounds__(256) void degdis_kernel(int N) {
    int node = (blockIdx.x * blockDim.x + threadIdx.x) >> 5;
    int lane = threadIdx.x & 31;
    if (node >= N) return;
    int start = g_off[node];
    int end   = g_off[node + 1];
    float s = 0.f;
    for (int e = start + lane; e < end; e += 32)
        s += __uint_as_float((unsigned int)(g_csr[e] >> 32));
    #pragma unroll
    for (int m = 1; m < 32; m <<= 1)
        s += __shfl_xor_sync(0xffffffffu, s, m);
    float dis = rsqrtf(s + 1.0f);        // +1: self-loop weight
    if (lane == 0) g_dis[node] = dis;
    if (lane < 4) {                       // h1 *= dis  (hd = dis*h)
        float4 h = g_h1[node * 4 + lane];
        g_h1[node * 4 + lane] = make_float4(dis * h.x, dis * h.y, dis * h.z, dis * h.w);
    }
}

// ---------------- gather layer 1: hd2 = dis*relu(dis*(Σ w·hd[r] + hd[c])+b1)-
__global__ __launch_bounds__(256) void gather1_kernel(const float* __restrict__ bias, int N) {
    int node = (blockIdx.x * blockDim.x + threadIdx.x) >> 5;
    int lane = threadIdx.x & 31;
    if (node >= N) return;

    int start = g_off[node];
    int end   = g_off[node + 1];
    int sub = lane >> 2;     // 0..7 : edge slot
    int q   = lane & 3;      // 0..3 : float4 quad

    float4 acc = make_float4(0.f, 0.f, 0.f, 0.f);
    for (int e = start + sub; e < end; e += 8) {
        unsigned long long en = g_csr[e];
        int   r = (int)(unsigned int)(en & 0xffffffffULL);
        float w = __uint_as_float((unsigned int)(en >> 32));
        float4 s = g_h1[r * 4 + q];
        acc.x = fmaf(w, s.x, acc.x);
        acc.y = fmaf(w, s.y, acc.y);
        acc.z = fmaf(w, s.z, acc.z);
        acc.w = fmaf(w, s.w, acc.w);
    }
    #pragma unroll
    for (int m = 4; m < 32; m <<= 1) {
        acc.x += __shfl_xor_sync(0xffffffffu, acc.x, m);
        acc.y += __shfl_xor_sync(0xffffffffu, acc.y, m);
        acc.z += __shfl_xor_sync(0xffffffffu, acc.z, m);
        acc.w += __shfl_xor_sync(0xffffffffu, acc.w, m);
    }
    if (lane < 4) {
        float dis = g_dis[node];
        float4 h = g_h1[node * 4 + lane];      // hd[node]: self-loop term
        float4 b = ((const float4*)bias)[lane];
        acc.x = dis * fmaxf(fmaf(dis, acc.x + h.x, b.x), 0.f);
        acc.y = dis * fmaxf(fmaf(dis, acc.y + h.y, b.y), 0.f);
        acc.z = dis * fmaxf(fmaf(dis, acc.z + h.z, b.z), 0.f);
        acc.w = dis * fmaxf(fmaf(dis, acc.w + h.w, b.w), 0.f);
        g_h2[node * 4 + lane] = acc;
    }
}

// ---------------- fused gather layer 2 + W2 GEMM + log_softmax --------------
__global__ __launch_bounds__(256) void gatherfinal_kernel(const float* __restrict__ W2,
                                                          const float* __restrict__ b2,
                                                          float* __restrict__ out,
                                                          int N) {
    __shared__ float w2s[HID][CLS];
    __shared__ float b2s[CLS];
    for (int i = threadIdx.x; i < HID * CLS; i += blockDim.x)
        w2s[i / CLS][i % CLS] = W2[i];
    if (threadIdx.x < CLS) b2s[threadIdx.x] = b2[threadIdx.x];
    __syncthreads();

    int node = (blockIdx.x * blockDim.x + threadIdx.x) >> 5;
    int lane = threadIdx.x & 31;
    if (node >= N) return;

    int start = g_off[node];
    int end   = g_off[node + 1];
    int sub = lane >> 2;
    int q   = lane & 3;

    float4 acc = make_float4(0.f, 0.f, 0.f, 0.f);
    for (int e = start + sub; e < end; e += 8) {
        unsigned long long en = g_csr[e];
        int   r = (int)(unsigned int)(en & 0xffffffffULL);
        float w = __uint_as_float((unsigned int)(en >> 32));
        float4 s = g_h2[r * 4 + q];
        acc.x = fmaf(w, s.x, acc.x);
        acc.y = fmaf(w, s.y, acc.y);
        acc.z = fmaf(w, s.z, acc.z);
        acc.w = fmaf(w, s.w, acc.w);
    }
    #pragma unroll
    for (int m = 4; m < 32; m <<= 1) {
        acc.x += __shfl_xor_sync(0xffffffffu, acc.x, m);
        acc.y += __shfl_xor_sync(0xffffffffu, acc.y, m);
        acc.z += __shfl_xor_sync(0xffffffffu, acc.z, m);
        acc.w += __shfl_xor_sync(0xffffffffu, acc.w, m);
    }
    // t_quad = dis*(acc + hd2[node])  (every lane holds its q's reduced quad)
    float dis = g_dis[node];
    float4 h = g_h2[node * 4 + q];
    acc.x = dis * (acc.x + h.x);
    acc.y = dis * (acc.y + h.y);
    acc.z = dis * (acc.z + h.z);
    acc.w = dis * (acc.w + h.w);

    // broadcast t[16]: lane j (j<4) holds quad j
    float t[HID];
    #pragma unroll
    for (int j = 0; j < 4; j++) {
        t[4*j+0] = __shfl_sync(0xffffffffu, acc.x, j);
        t[4*j+1] = __shfl_sync(0xffffffffu, acc.y, j);
        t[4*j+2] = __shfl_sync(0xffffffffu, acc.z, j);
        t[4*j+3] = __shfl_sync(0xffffffffu, acc.w, j);
    }

    float o1 = b2s[lane];
    float o2 = (lane < 8) ? b2s[32 + lane] : -1e30f;
    #pragma unroll
    for (int k = 0; k < HID; k++) {
        o1 = fmaf(t[k], w2s[k][lane], o1);
        if (lane < 8) o2 = fmaf(t[k], w2s[k][32 + lane], o2);
    }

    float m = fmaxf(o1, o2);
    #pragma unroll
    for (int d = 1; d < 32; d <<= 1) m = fmaxf(m, __shfl_xor_sync(0xffffffffu, m, d));
    float s = expf(o1 - m) + ((lane < 8) ? expf(o2 - m) : 0.f);
    #pragma unroll
    for (int d = 1; d < 32; d <<= 1) s += __shfl_xor_sync(0xffffffffu, s, d);
    float lse = m + logf(s);

    float* o = out + (size_t)node * CLS;
    o[lane] = o1 - lse;
    if (lane < 8) o[32 + lane] = o2 - lse;
}

// ---------------------------------------------------------------------------
extern "C" void kernel_launch(void* const* d_in, const int* in_sizes, int n_in,
                              void* d_out, int out_size) {
    const float* x  = (const float*)d_in[0];
    const int*   ei = (const int*)d_in[1];
    const float* ew = (const float*)d_in[2];
    const float* W1 = (const float*)d_in[3];
    const float* b1 = (const float*)d_in[4];
    const float* W2 = (const float*)d_in[5];
    const float* b2 = (const float*)d_in[6];
    float* out = (float*)d_out;

    int N = in_sizes[0] / F_IN;     // 100000
    int E = in_sizes[2];            // 3200000

    const int T = 256;
    dim3 ggrid((N + ROWS_B - 1) / ROWS_B, KSPLIT);
    init_kernel<<<(N * 4 + T - 1) / T, T>>>(N);                  // 0
    cnt_kernel<<<(E + T - 1) / T, T>>>(ei + E, E);               // 1
    scan1_kernel<<<NBLK, SCAN_B>>>(N);                           // 2
    gemm1_kernel<<<ggrid, GT>>>(x, W1, N);                       // 3 (profiled)
    scan2_kernel<<<1, 128>>>(N);                                 // 4
    scan3_kernel<<<(N + T - 1) / T, T>>>(N);                     // 5
    fill_kernel<<<(E + T - 1) / T, T>>>(ei, ew, E);              // 6
    degdis_kernel<<<(N * 32 + T - 1) / T, T>>>(N);               // 7
    gather1_kernel<<<(N * 32 + T - 1) / T, T>>>(b1, N);          // 8
    gatherfinal_kernel<<<(N * 32 + T - 1) / T, T>>>(W2, b2, out, N); // 9
}

// round 16
// speedup vs baseline: 1.0146x; 1.0146x over previous
#include <cuda_runtime.h>
#include <math.h>

#define F_IN   512
#define HID    16
#define CLS    40
#define N_MAX  100000
#define E_MAX  3400000
#define SCAN_B 1024
#define NBLK   ((N_MAX + SCAN_B - 1) / SCAN_B)   // 98

// ---------------- scratch (static device globals; no allocation) ------------
__device__ float  g_dis[N_MAX];                 // dis = rsqrt(deg)
__device__ int    g_cnt[N_MAX];                 // in-degree counts
__device__ int    g_off[N_MAX + 1];             // CSR offsets (by col)
__device__ int    g_cursor[N_MAX];              // fill cursors
__device__ int    g_bsum[NBLK];                 // per-block totals
__device__ int    g_boff[NBLK];                 // per-block exclusive offsets
__device__ unsigned long long g_csr[E_MAX];     // packed (w_bits<<32 | row)
__device__ float4 g_h1[N_MAX * 4];              // h1 partials, then dis*h1
__device__ float4 g_h2[N_MAX * 4];              // hd2 = dis*relu(layer1)

// ---------------- helpers ---------------------------------------------------
__device__ __forceinline__ unsigned long long pack2(float lo, float hi) {
    unsigned long long d;
    asm("mov.b64 %0, {%1,%2};" : "=l"(d) : "f"(lo), "f"(hi));
    return d;
}
__device__ __forceinline__ void unpack2(unsigned long long v, float& lo, float& hi) {
    asm("mov.b64 {%0,%1}, %2;" : "=f"(lo), "=f"(hi) : "l"(v));
}
__device__ __forceinline__ unsigned long long fma2(unsigned long long a,
                                                   unsigned long long b,
                                                   unsigned long long c) {
    unsigned long long d;
    asm("fma.rn.f32x2 %0, %1, %2, %3;" : "=l"(d) : "l"(a), "l"(b), "l"(c));
    return d;
}
__device__ __forceinline__ void red_add_v4(float4* addr, float x, float y, float z, float w) {
    asm volatile("red.global.add.v4.f32 [%0], {%1,%2,%3,%4};"
                 :: "l"(addr), "f"(x), "f"(y), "f"(z), "f"(w)
                 : "memory");
}

// ---------------- init: cnt=0, h1=0 (red.add target) ------------------------
__global__ void init_kernel(int N) {
    int i = blockIdx.x * blockDim.x + threadIdx.x;
    if (i < N * 4) g_h1[i] = make_float4(0.f, 0.f, 0.f, 0.f);
    if (i < N) g_cnt[i] = 0;
}

// cnt[col] += 1
__global__ void cnt_kernel(const int* __restrict__ col, int E) {
    int e = blockIdx.x * blockDim.x + threadIdx.x;
    if (e < E) atomicAdd(&g_cnt[col[e]], 1);
}

// ---------------- 3-phase multi-block exclusive scan ------------------------
__global__ __launch_bounds__(SCAN_B) void scan1_kernel(int N) {
    __shared__ int s[SCAN_B];
    int t = threadIdx.x;
    int i = blockIdx.x * SCAN_B + t;
    int v = (i < N) ? g_cnt[i] : 0;
    s[t] = v;
    __syncthreads();
    #pragma unroll
    for (int d = 1; d < SCAN_B; d <<= 1) {
        int u = (t >= d) ? s[t - d] : 0;
        __syncthreads();
        s[t] += u;
        __syncthreads();
    }
    if (i < N) g_off[i] = s[t] - v;                 // exclusive
    if (t == SCAN_B - 1) g_bsum[blockIdx.x] = s[t]; // block total
}

__global__ __launch_bounds__(128) void scan2_kernel(int N) {
    __shared__ int s[128];
    int t = threadIdx.x;
    int v = (t < NBLK) ? g_bsum[t] : 0;
    s[t] = v;
    __syncthreads();
    #pragma unroll
    for (int d = 1; d < 128; d <<= 1) {
        int u = (t >= d) ? s[t - d] : 0;
        __syncthreads();
        s[t] += u;
        __syncthreads();
    }
    if (t < NBLK) g_boff[t] = s[t] - v;
    if (t == 127) g_off[N] = s[t];                  // grand total (= E)
}

__global__ void scan3_kernel(int N) {
    int i = blockIdx.x * blockDim.x + threadIdx.x;
    if (i < N) {
        int o = g_off[i] + g_boff[i / SCAN_B];
        g_off[i] = o;
        g_cursor[i] = o;
    }
}

// fill CSR: append (w, row) to col c
__global__ void fill_kernel(const int* __restrict__ ei, const float* __restrict__ w, int E) {
    int e = blockIdx.x * blockDim.x + threadIdx.x;
    if (e >= E) return;
    int r = ei[e];
    int c = ei[E + e];
    int pos = atomicAdd(&g_cursor[c], 1);
    g_csr[pos] = ((unsigned long long)__float_as_uint(w[e]) << 32) | (unsigned int)r;
}

// ---------------- dense GEMM: h1 += x @ W1 (cp.async double-buffer) ---------
#define GT     256                 // threads per block (8 warps)
#define ROWS_B 512                 // rows per block = 256 packed pairs
#define KC     16                  // k-chunk
#define XPAD   4                   // row stride 20 floats: conflict-free LDS.128
#define KSPLIT 4
#define KPB    (F_IN / KSPLIT)     // 128 K per block
#define NCHUNK (KPB / KC)          // 8
#define XS_FLOATS (ROWS_B * (KC + XPAD))                 // 10240 floats / buffer
#define GEMM_SMEM (2 * XS_FLOATS * 4 + KPB * HID * 8)    // 81920 + 16384 = 98304 B

__global__ __launch_bounds__(GT) void gemm1_kernel(const float* __restrict__ x,
                                                   const float* __restrict__ W1,
                                                   int N) {
    extern __shared__ char sm[];
    float* xsf = (float*)sm;                                        // [2][XS_FLOATS]
    unsigned long long (*ws2)[HID] =
        (unsigned long long(*)[HID])(sm + 2 * XS_FLOATS * 4);       // [KPB][HID]

    int r0 = blockIdx.x * ROWS_B;
    int k0 = blockIdx.y * KPB;

    // kick off chunk 0 loads first (get DRAM busy), then stage weights
    {
        #pragma unroll
        for (int l = 0; l < (ROWS_B * (KC / 4)) / GT; l++) {   // 8 cp.async each
            int idx = l * GT + threadIdx.x;
            int rl  = idx / (KC / 4);
            int c4  = idx % (KC / 4);
            int row = r0 + rl;
            unsigned sdst = (unsigned)__cvta_generic_to_shared(&xsf[rl * (KC + XPAD) + c4 * 4]);
            const float* src = x + (size_t)row * F_IN + k0 + c4 * 4;
            int sz = (row < N) ? 16 : 0;
            asm volatile("cp.async.cg.shared.global [%0], [%1], 16, %2;"
                         :: "r"(sdst), "l"(src), "r"(sz));
        }
        asm volatile("cp.async.commit_group;" ::: "memory");
    }
    // pre-duplicate the whole 128x16 W slab once (8 per thread)
    for (int i = threadIdx.x; i < KPB * HID; i += GT) {
        float wv = W1[(size_t)(k0 + i / HID) * HID + (i % HID)];
        ws2[i / HID][i % HID] = pack2(wv, wv);
    }

    unsigned long long acc2[HID];
    #pragma unroll
    for (int j = 0; j < HID; j++) acc2[j] = 0ULL;

    #pragma unroll 1
    for (int c = 0; c < NCHUNK; c++) {
        // prefetch chunk c+1 into the other buffer (safe: its last reader was
        // chunk c-1's compute, fenced by the trailing __syncthreads below)
        if (c + 1 < NCHUNK) {
            int kc = k0 + (c + 1) * KC;
            float* dstbuf = xsf + ((c + 1) & 1) * XS_FLOATS;
            #pragma unroll
            for (int l = 0; l < (ROWS_B * (KC / 4)) / GT; l++) {
                int idx = l * GT + threadIdx.x;
                int rl  = idx / (KC / 4);
                int c4  = idx % (KC / 4);
                int row = r0 + rl;
                unsigned sdst = (unsigned)__cvta_generic_to_shared(&dstbuf[rl * (KC + XPAD) + c4 * 4]);
                const float* src = x + (size_t)row * F_IN + kc + c4 * 4;
                int sz = (row < N) ? 16 : 0;
                asm volatile("cp.async.cg.shared.global [%0], [%1], 16, %2;"
                             :: "r"(sdst), "l"(src), "r"(sz));
            }
            asm volatile("cp.async.commit_group;" ::: "memory");
            asm volatile("cp.async.wait_group 1;" ::: "memory");   // chunk c done
        } else {
            asm volatile("cp.async.wait_group 0;" ::: "memory");   // drain all
        }
        __syncthreads();

        const float* buf = xsf + (c & 1) * XS_FLOATS;
        const unsigned long long (*wrow)[HID] = &ws2[c * KC];
        #pragma unroll
        for (int k4 = 0; k4 < KC / 4; k4++) {
            float4 xa4 = *(const float4*)&buf[threadIdx.x * (KC + XPAD) + k4 * 4];
            float4 xb4 = *(const float4*)&buf[(threadIdx.x + 256) * (KC + XPAD) + k4 * 4];
            float xa[4] = {xa4.x, xa4.y, xa4.z, xa4.w};
            float xb[4] = {xb4.x, xb4.y, xb4.z, xb4.w};
            #pragma unroll
            for (int ki = 0; ki < 4; ki++) {
                int kk = k4 * 4 + ki;
                unsigned long long xp = pack2(xa[ki], xb[ki]);
                #pragma unroll
                for (int m = 0; m < HID / 2; m++) {
                    ulonglong2 w2 = *(const ulonglong2*)&wrow[kk][2 * m];
                    acc2[2 * m + 0] = fma2(xp, w2.x, acc2[2 * m + 0]);
                    acc2[2 * m + 1] = fma2(xp, w2.y, acc2[2 * m + 1]);
                }
            }
        }
        __syncthreads();
    }

    float va[HID], vb[HID];
    #pragma unroll
    for (int j = 0; j < HID; j++) unpack2(acc2[j], va[j], vb[j]);
    int rowA = r0 + threadIdx.x;
    int rowB = r0 + threadIdx.x + 256;
    if (rowA < N) {
        #pragma unroll
        for (int q = 0; q < 4; q++)
            red_add_v4(&g_h1[rowA * 4 + q], va[4*q], va[4*q+1], va[4*q+2], va[4*q+3]);
    }
    if (rowB < N) {
        #pragma unroll
        for (int q = 0; q < 4; q++)
            red_add_v4(&g_h1[rowB * 4 + q], vb[4*q], vb[4*q+1], vb[4*q+2], vb[4*q+3]);
    }
}

// ---------------- deg from CSR; dis = rsqrt; scale h1 *= dis (warp/node) ----
__global__ __launch_bounds__(256) void degdis_kernel(int N) {
    int node = (blockIdx.x * blockDim.x + threadIdx.x) >> 5;
    int lane = threadIdx.x & 31;
    if (node >= N) return;
    int start = g_off[node];
    int end   = g_off[node + 1];
    float s = 0.f;
    for (int e = start + lane; e < end; e += 32)
        s += __uint_as_float((unsigned int)(g_csr[e] >> 32));
    #pragma unroll
    for (int m = 1; m < 32; m <<= 1)
        s += __shfl_xor_sync(0xffffffffu, s, m);
    float dis = rsqrtf(s + 1.0f);        // +1: self-loop weight
    if (lane == 0) g_dis[node] = dis;
    if (lane < 4) {                       // h1 *= dis  (hd = dis*h)
        float4 h = g_h1[node * 4 + lane];
        g_h1[node * 4 + lane] = make_float4(dis * h.x, dis * h.y, dis * h.z, dis * h.w);
    }
}

// ---------------- gather layer 1: hd2 = dis*relu(dis*(Σ w·hd[r] + hd[c])+b1)-
__global__ __launch_bounds__(256) void gather1_kernel(const float* __restrict__ bias, int N) {
    int node = (blockIdx.x * blockDim.x + threadIdx.x) >> 5;
    int lane = threadIdx.x & 31;
    if (node >= N) return;

    int start = g_off[node];
    int end   = g_off[node + 1];
    int sub = lane >> 2;     // 0..7 : edge slot
    int q   = lane & 3;      // 0..3 : float4 quad

    float4 acc = make_float4(0.f, 0.f, 0.f, 0.f);
    for (int e = start + sub; e < end; e += 8) {
        unsigned long long en = g_csr[e];
        int   r = (int)(unsigned int)(en & 0xffffffffULL);
        float w = __uint_as_float((unsigned int)(en >> 32));
        float4 s = g_h1[r * 4 + q];
        acc.x = fmaf(w, s.x, acc.x);
        acc.y = fmaf(w, s.y, acc.y);
        acc.z = fmaf(w, s.z, acc.z);
        acc.w = fmaf(w, s.w, acc.w);
    }
    #pragma unroll
    for (int m = 4; m < 32; m <<= 1) {
        acc.x += __shfl_xor_sync(0xffffffffu, acc.x, m);
        acc.y += __shfl_xor_sync(0xffffffffu, acc.y, m);
        acc.z += __shfl_xor_sync(0xffffffffu, acc.z, m);
        acc.w += __shfl_xor_sync(0xffffffffu, acc.w, m);
    }
    if (lane < 4) {
        float dis = g_dis[node];
        float4 h = g_h1[node * 4 + lane];      // hd[node]: self-loop term
        float4 b = ((const float4*)bias)[lane];
        acc.x = dis * fmaxf(fmaf(dis, acc.x + h.x, b.x), 0.f);
        acc.y = dis * fmaxf(fmaf(dis, acc.y + h.y, b.y), 0.f);
        acc.z = dis * fmaxf(fmaf(dis, acc.z + h.z, b.z), 0.f);
        acc.w = dis * fmaxf(fmaf(dis, acc.w + h.w, b.w), 0.f);
        g_h2[node * 4 + lane] = acc;
    }
}

// ---------------- fused gather layer 2 + W2 GEMM + log_softmax --------------
__global__ __launch_bounds__(256) void gatherfinal_kernel(const float* __restrict__ W2,
                                                          const float* __restrict__ b2,
                                                          float* __restrict__ out,
                                                          int N) {
    __shared__ float w2s[HID][CLS];
    __shared__ float b2s[CLS];
    for (int i = threadIdx.x; i < HID * CLS; i += blockDim.x)
        w2s[i / CLS][i % CLS] = W2[i];
    if (threadIdx.x < CLS) b2s[threadIdx.x] = b2[threadIdx.x];
    __syncthreads();

    int node = (blockIdx.x * blockDim.x + threadIdx.x) >> 5;
    int lane = threadIdx.x & 31;
    if (node >= N) return;

    int start = g_off[node];
    int end   = g_off[node + 1];
    int sub = lane >> 2;
    int q   = lane & 3;

    float4 acc = make_float4(0.f, 0.f, 0.f, 0.f);
    for (int e = start + sub; e < end; e += 8) {
        unsigned long long en = g_csr[e];
        int   r = (int)(unsigned int)(en & 0xffffffffULL);
        float w = __uint_as_float((unsigned int)(en >> 32));
        float4 s = g_h2[r * 4 + q];
        acc.x = fmaf(w, s.x, acc.x);
        acc.y = fmaf(w, s.y, acc.y);
        acc.z = fmaf(w, s.z, acc.z);
        acc.w = fmaf(w, s.w, acc.w);
    }
    #pragma unroll
    for (int m = 4; m < 32; m <<= 1) {
        acc.x += __shfl_xor_sync(0xffffffffu, acc.x, m);
        acc.y += __shfl_xor_sync(0xffffffffu, acc.y, m);
        acc.z += __shfl_xor_sync(0xffffffffu, acc.z, m);
        acc.w += __shfl_xor_sync(0xffffffffu, acc.w, m);
    }
    // t_quad = dis*(acc + hd2[node])  (every lane holds its q's reduced quad)
    float dis = g_dis[node];
    float4 h = g_h2[node * 4 + q];
    acc.x = dis * (acc.x + h.x);
    acc.y = dis * (acc.y + h.y);
    acc.z = dis * (acc.z + h.z);
    acc.w = dis * (acc.w + h.w);

    // broadcast t[16]: lane j (j<4) holds quad j
    float t[HID];
    #pragma unroll
    for (int j = 0; j < 4; j++) {
        t[4*j+0] = __shfl_sync(0xffffffffu, acc.x, j);
        t[4*j+1] = __shfl_sync(0xffffffffu, acc.y, j);
        t[4*j+2] = __shfl_sync(0xffffffffu, acc.z, j);
        t[4*j+3] = __shfl_sync(0xffffffffu, acc.w, j);
    }

    float o1 = b2s[lane];
    float o2 = (lane < 8) ? b2s[32 + lane] : -1e30f;
    #pragma unroll
    for (int k = 0; k < HID; k++) {
        o1 = fmaf(t[k], w2s[k][lane], o1);
        if (lane < 8) o2 = fmaf(t[k], w2s[k][32 + lane], o2);
    }

    float m = fmaxf(o1, o2);
    #pragma unroll
    for (int d = 1; d < 32; d <<= 1) m = fmaxf(m, __shfl_xor_sync(0xffffffffu, m, d));
    float s = expf(o1 - m) + ((lane < 8) ? expf(o2 - m) : 0.f);
    #pragma unroll
    for (int d = 1; d < 32; d <<= 1) s += __shfl_xor_sync(0xffffffffu, s, d);
    float lse = m + logf(s);

    float* o = out + (size_t)node * CLS;
    o[lane] = o1 - lse;
    if (lane < 8) o[32 + lane] = o2 - lse;
}

// ---------------------------------------------------------------------------
extern "C" void kernel_launch(void* const* d_in, const int* in_sizes, int n_in,
                              void* d_out, int out_size) {
    const float* x  = (const float*)d_in[0];
    const int*   ei = (const int*)d_in[1];
    const float* ew = (const float*)d_in[2];
    const float* W1 = (const float*)d_in[3];
    const float* b1 = (const float*)d_in[4];
    const float* W2 = (const float*)d_in[5];
    const float* b2 = (const float*)d_in[6];
    float* out = (float*)d_out;

    int N = in_sizes[0] / F_IN;     // 100000
    int E = in_sizes[2];            // 3200000

    cudaFuncSetAttribute(gemm1_kernel,
                         cudaFuncAttributeMaxDynamicSharedMemorySize, GEMM_SMEM);

    const int T = 256;
    dim3 ggrid((N + ROWS_B - 1) / ROWS_B, KSPLIT);
    init_kernel<<<(N * 4 + T - 1) / T, T>>>(N);                  // 0
    cnt_kernel<<<(E + T - 1) / T, T>>>(ei + E, E);               // 1
    scan1_kernel<<<NBLK, SCAN_B>>>(N);                           // 2
    gemm1_kernel<<<ggrid, GT, GEMM_SMEM>>>(x, W1, N);            // 3 (profiled)
    scan2_kernel<<<1, 128>>>(N);                                 // 4
    scan3_kernel<<<(N + T - 1) / T, T>>>(N);                     // 5
    fill_kernel<<<(E + T - 1) / T, T>>>(ei, ew, E);              // 6
    degdis_kernel<<<(N * 32 + T - 1) / T, T>>>(N);               // 7
    gather1_kernel<<<(N * 32 + T - 1) / T, T>>>(b1, N);          // 8
    gatherfinal_kernel<<<(N * 32 + T - 1) / T, T>>>(W2, b2, out, N); // 9
}